// round 1
// baseline (speedup 1.0000x reference)
#include <cuda_runtime.h>
#include <cstdint>
#include <math_constants.h>

#define A_NUM 9
#define H_DIM 128
#define W_DIM 192
#define NTOT (H_DIM*W_DIM*A_NUM)   // 221184
#define PRE_NMS 6000
#define POST_NMS 300
#define NBINS 4096
#define CAND_CAP 16384
#define MASK_WORDS ((PRE_NMS+63)/64)   // 94
#define NMS_THR 0.7f

__constant__ float c_anchors[A_NUM][4] = {
    {-84.f,  -40.f,  99.f,  55.f},
    {-176.f, -88.f,  191.f, 103.f},
    {-360.f, -184.f, 375.f, 199.f},
    {-56.f,  -56.f,  71.f,  71.f},
    {-120.f, -120.f, 135.f, 135.f},
    {-248.f, -248.f, 263.f, 263.f},
    {-36.f,  -80.f,  51.f,  95.f},
    {-80.f,  -168.f, 95.f,  183.f},
    {-168.f, -344.f, 183.f, 359.f}};

__device__ float4 g_boxes[NTOT];
__device__ float  g_scores[NTOT];
__device__ int    g_hist[NBINS];
__device__ int    g_thr;
__device__ int    g_numCand;
__device__ unsigned long long g_candKeys[CAND_CAP];
__device__ unsigned long long g_sortedKeys[PRE_NMS];
__device__ float4 g_boxesS[PRE_NMS];
__device__ int    g_valid[PRE_NMS];
__device__ unsigned long long g_mask[PRE_NMS * MASK_WORDS];

// ---------------------------------------------------------------- zero scratch
__global__ void k_zero() {
    int i = blockIdx.x * blockDim.x + threadIdx.x;
    if (i < NBINS) g_hist[i] = 0;
    if (i < PRE_NMS) g_sortedKeys[i] = 0ULL;
    if (i == 0) g_numCand = 0;
}

// ---------------------------------------------------------------- box decode
__global__ void k_prep(const float* __restrict__ scores,
                       const float* __restrict__ deltas,
                       const float* __restrict__ im_info) {
    int i = blockIdx.x * blockDim.x + threadIdx.x;
    if (i >= NTOT) return;
    int a = i % A_NUM;
    int pix = i / A_NUM;
    int x = pix % W_DIM;
    int y = pix / W_DIM;
    const int HW = H_DIM * W_DIM;
    int p = y * W_DIM + x;

    float sc = scores[(A_NUM + a) * HW + p];
    float dx = deltas[(4 * a + 0) * HW + p];
    float dy = deltas[(4 * a + 1) * HW + p];
    float dw = deltas[(4 * a + 2) * HW + p];
    float dh = deltas[(4 * a + 3) * HW + p];
    dw = fminf(fmaxf(dw, -10.f), 10.f);
    dh = fminf(fmaxf(dh, -10.f), 10.f);

    float sx = (float)x * 16.f;
    float sy = (float)y * 16.f;
    float ax1 = c_anchors[a][0] + sx;
    float ay1 = c_anchors[a][1] + sy;
    float ax2 = c_anchors[a][2] + sx;
    float ay2 = c_anchors[a][3] + sy;
    float wdt = ax2 - ax1 + 1.f;
    float hgt = ay2 - ay1 + 1.f;
    float cx = ax1 + 0.5f * wdt;
    float cy = ay1 + 0.5f * hgt;

    float pcx = dx * wdt + cx;
    float pcy = dy * hgt + cy;
    float pw = expf(dw) * wdt;
    float ph = expf(dh) * hgt;

    float imH = im_info[0], imW = im_info[1], sc_im = im_info[2];
    float x1 = pcx - 0.5f * pw;
    float y1 = pcy - 0.5f * ph;
    float x2 = pcx + 0.5f * pw;
    float y2 = pcy + 0.5f * ph;
    x1 = fminf(fmaxf(x1, 0.f), imW - 1.f);
    x2 = fminf(fmaxf(x2, 0.f), imW - 1.f);
    y1 = fminf(fmaxf(y1, 0.f), imH - 1.f);
    y2 = fminf(fmaxf(y2, 0.f), imH - 1.f);

    g_boxes[i] = make_float4(x1, y1, x2, y2);
    float minsz = 16.f * sc_im;
    bool valid = (x2 - x1 + 1.f >= minsz) && (y2 - y1 + 1.f >= minsz);
    g_scores[i] = valid ? sc : -CUDART_INF_F;
    if (valid) {
        int bin = (int)(sc * (float)NBINS);
        bin = max(0, min(NBINS - 1, bin));
        atomicAdd(&g_hist[bin], 1);
    }
}

// ---------------------------------------------------------------- histogram threshold
__global__ void k_thresh() {
    __shared__ int sh[NBINS];
    for (int b = threadIdx.x; b < NBINS; b += blockDim.x) sh[b] = g_hist[b];
    __syncthreads();
    if (threadIdx.x == 0) {
        int cum = 0, thr = 0;
        for (int b = NBINS - 1; b >= 0; b--) {
            cum += sh[b];
            if (cum >= PRE_NMS) { thr = b; break; }
        }
        g_thr = thr;
    }
}

// ---------------------------------------------------------------- candidate compaction
__global__ void k_filter() {
    int i = blockIdx.x * blockDim.x + threadIdx.x;
    if (i >= NTOT) return;
    float s = g_scores[i];
    if (!(s >= 0.0f)) return;   // invalid -> -inf
    int bin = (int)(s * (float)NBINS);
    bin = max(0, min(NBINS - 1, bin));
    if (bin < g_thr) return;
    int p = atomicAdd(&g_numCand, 1);
    if (p < CAND_CAP) {
        unsigned long long key =
            ((unsigned long long)__float_as_uint(s) << 32) |
            (unsigned long long)(~(unsigned)i);
        g_candKeys[p] = key;
    }
}

// ---------------------------------------------------------------- exact ranking sort
__global__ void k_rank() {
    __shared__ unsigned long long tile[2048];
    int i = blockIdx.x * blockDim.x + threadIdx.x;
    int n = min(g_numCand, CAND_CAP);
    unsigned long long my = (i < n) ? g_candKeys[i] : 0ULL;
    int rank = 0;
    for (int base = 0; base < n; base += 2048) {
        int cnt = min(2048, n - base);
        for (int j = threadIdx.x; j < cnt; j += blockDim.x)
            tile[j] = g_candKeys[base + j];
        __syncthreads();
        for (int j = 0; j < cnt; j++)
            rank += (tile[j] > my) ? 1 : 0;
        __syncthreads();
    }
    if (i < n && rank < PRE_NMS) g_sortedKeys[rank] = my;
}

// ---------------------------------------------------------------- gather sorted boxes
__global__ void k_gather() {
    int r = blockIdx.x * blockDim.x + threadIdx.x;
    if (r >= PRE_NMS) return;
    unsigned long long key = g_sortedKeys[r];
    if (key != 0ULL) {
        unsigned idx = ~(unsigned)(key & 0xffffffffULL);
        g_boxesS[r] = g_boxes[idx];
        g_valid[r] = 1;
    } else {
        g_boxesS[r] = make_float4(0.f, 0.f, 0.f, 0.f);
        g_valid[r] = 0;
    }
}

// ---------------------------------------------------------------- NMS bitmask (upper triangle)
__global__ void k_mask() {
    int bi = blockIdx.y;   // row block (i)
    int bj = blockIdx.x;   // col block (j)
    if (bj < bi) return;   // only j > i needed
    __shared__ float4 jb[64];
    int jbase = bj * 64;
    int t = threadIdx.x;
    if (jbase + t < PRE_NMS) jb[t] = g_boxesS[jbase + t];
    else jb[t] = make_float4(0.f, 0.f, 0.f, 0.f);
    __syncthreads();

    int i = bi * 64 + t;
    if (i >= PRE_NMS) return;
    float4 b1 = g_boxesS[i];
    float areaI = (b1.z - b1.x) * (b1.w - b1.y);
    unsigned long long bits = 0ULL;
    #pragma unroll 4
    for (int j = 0; j < 64; j++) {
        int jj = jbase + j;
        if (jj <= i || jj >= PRE_NMS) continue;
        float4 b2 = jb[j];
        float areaJ = (b2.z - b2.x) * (b2.w - b2.y);
        float lx = fmaxf(b1.x, b2.x);
        float ly = fmaxf(b1.y, b2.y);
        float rx = fminf(b1.z, b2.z);
        float ry = fminf(b1.w, b2.w);
        float w = fmaxf(rx - lx, 0.f);
        float h = fmaxf(ry - ly, 0.f);
        float inter = w * h;
        float iou = inter / (areaI + areaJ - inter);
        if (iou > NMS_THR) bits |= (1ULL << j);
    }
    g_mask[(size_t)i * MASK_WORDS + bj] = bits;
}

// ---------------------------------------------------------------- serial greedy scan (1 warp)
__global__ void k_scan(float* __restrict__ out) {
    __shared__ unsigned long long remv[MASK_WORDS];
    int t = threadIdx.x;
    for (int w = t; w < MASK_WORDS; w += 32) remv[w] = 0ULL;
    __syncwarp();
    int kcount = 0;
    for (int i = 0; i < PRE_NMS; i++) {
        int keep = 0;
        if (t == 0) {
            int v = g_valid[i];
            int sup = (int)((remv[i >> 6] >> (i & 63)) & 1ULL);
            keep = v && !sup;
        }
        keep = __shfl_sync(0xffffffff, keep, 0);
        if (keep) {
            if (t == 0) {
                float4 b = g_boxesS[i];
                out[kcount * 5 + 0] = 0.f;
                out[kcount * 5 + 1] = b.x;
                out[kcount * 5 + 2] = b.y;
                out[kcount * 5 + 3] = b.z;
                out[kcount * 5 + 4] = b.w;
            }
            kcount++;
            if (kcount >= POST_NMS) break;   // later kept boxes never reach output
            int w0 = i >> 6;
            for (int w = w0 + t; w < MASK_WORDS; w += 32)
                remv[w] |= g_mask[(size_t)i * MASK_WORDS + w];
        }
        __syncwarp();
    }
    __syncwarp();
    // zero-fill remaining rows
    int startF = min(kcount, POST_NMS) * 5;
    for (int k = startF + t; k < POST_NMS * 5; k += 32) out[k] = 0.f;
}

// ---------------------------------------------------------------- launch
extern "C" void kernel_launch(void* const* d_in, const int* in_sizes, int n_in,
                              void* d_out, int out_size) {
    const float* scores  = (const float*)d_in[0];
    const float* deltas  = (const float*)d_in[1];
    const float* im_info = (const float*)d_in[2];
    float* out = (float*)d_out;

    k_zero<<<(PRE_NMS + 255) / 256 + 16, 256>>>();
    k_prep<<<NTOT / 256, 256>>>(scores, deltas, im_info);
    k_thresh<<<1, 1024>>>();
    k_filter<<<NTOT / 256, 256>>>();
    k_rank<<<CAND_CAP / 256, 256>>>();
    k_gather<<<(PRE_NMS + 255) / 256, 256>>>();
    dim3 mgrid(MASK_WORDS, MASK_WORDS);
    k_mask<<<mgrid, 64>>>();
    k_scan<<<1, 32>>>(out);
}